// round 11
// baseline (speedup 1.0000x reference)
#include <cuda_runtime.h>

#define BATCH 16384
#define EMBED 300
#define NCTX  10
#define NNEG  20
#define NSC   (1 + NNEG)   // 21 scores
#define NF4   75           // 300 floats = 75 float4 slots per row
#define WARPS_PER_BLOCK 8
#define BLOCK_THREADS   (WARPS_PER_BLOCK * 32)
#define GRID_BLOCKS     (BATCH / WARPS_PER_BLOCK)   // 2048
#define MIN_BLOCKS_SM   6

// fused-reduction state (zero-init .bss; last block resets for graph replays)
__device__ float        g_sum;
__device__ unsigned int g_arrived;

__device__ __forceinline__ float log_sigmoid(float x) {
    return fminf(x, 0.0f) - log1pf(__expf(-fabsf(x)));
}

__device__ __forceinline__ float dot4(float4 a, float4 b) {
    return a.x * b.x + a.y * b.y + a.z * b.z + a.w * b.w;
}

// ctx: stream through L2 (demoted so cen lines win the LRU race)
__device__ __forceinline__ unsigned long long policy_evict_first() {
    unsigned long long p;
    asm("createpolicy.fractional.L2::evict_first.b64 %0, 1.0;" : "=l"(p));
    return p;
}
// cen: pin HALF the accesses (≈58 MB stable hot subset — avoids oversubscribing
// the evict_last set-aside); the other half competes normally and still beats
// the demoted ctx stream.
__device__ __forceinline__ unsigned long long policy_evict_last_half() {
    unsigned long long p;
    asm("createpolicy.fractional.L2::evict_last.b64 %0, 0.5;" : "=l"(p));
    return p;
}

__device__ __forceinline__ float4 ldg_hint(const float4* p, unsigned long long pol) {
    float4 v;
    asm("ld.global.nc.L2::cache_hint.v4.f32 {%0,%1,%2,%3}, [%4], %5;"
        : "=f"(v.x), "=f"(v.y), "=f"(v.z), "=f"(v.w)
        : "l"(p), "l"(pol));
    return v;
}

__global__ __launch_bounds__(BLOCK_THREADS, MIN_BLOCKS_SM)
void cbow_fused_kernel(const int*   __restrict__ context,    // [B, NCTX]
                       const int*   __restrict__ center,     // [B]
                       const int*   __restrict__ negatives,  // [B, NNEG]
                       const float* __restrict__ ctx_w,      // [V, 300]
                       const float* __restrict__ cen_w,      // [V, 300]
                       float*       __restrict__ out)
{
    const int warp = threadIdx.x >> 5;
    const int lane = threadIdx.x & 31;
    const int b    = blockIdx.x * WARPS_PER_BLOCK + warp;

    const unsigned long long pol_stream   = policy_evict_first();
    const unsigned long long pol_resident = policy_evict_last_half();

    // ---- all 31 indices for this b, one per lane ----
    int idx = 0;
    if (lane < NCTX)            idx = context[b * NCTX + lane];
    else if (lane == NCTX)      idx = center[b];
    else if (lane < NCTX + NSC) idx = negatives[b * NNEG + (lane - NCTX - 1)];

    // ---- context mean: lane covers float4 slots {lane, lane+32, lane+64} ----
    float4 cm0 = make_float4(0.f, 0.f, 0.f, 0.f);
    float4 cm1 = cm0;
    float4 cm2 = cm0;
    const bool tail = (lane < NF4 - 64);   // lane < 11

    #pragma unroll
    for (int c = 0; c < NCTX; ++c) {
        int row = __shfl_sync(0xffffffffu, idx, c);
        const float4* r = reinterpret_cast<const float4*>(ctx_w + (size_t)row * EMBED);
        float4 a0 = ldg_hint(r + lane,      pol_stream);
        float4 a1 = ldg_hint(r + lane + 32, pol_stream);
        cm0.x += a0.x; cm0.y += a0.y; cm0.z += a0.z; cm0.w += a0.w;
        cm1.x += a1.x; cm1.y += a1.y; cm1.z += a1.z; cm1.w += a1.w;
        if (tail) {
            float4 a2 = ldg_hint(r + lane + 64, pol_stream);
            cm2.x += a2.x; cm2.y += a2.y; cm2.z += a2.z; cm2.w += a2.w;
        }
    }
    const float inv_c = 1.0f / (float)NCTX;
    cm0.x *= inv_c; cm0.y *= inv_c; cm0.z *= inv_c; cm0.w *= inv_c;
    cm1.x *= inv_c; cm1.y *= inv_c; cm1.z *= inv_c; cm1.w *= inv_c;
    cm2.x *= inv_c; cm2.y *= inv_c; cm2.z *= inv_c; cm2.w *= inv_c;

    // ---- 21 scores; each t terminates in smem (no cross-t register dep) ----
    __shared__ float sh_s[WARPS_PER_BLOCK][NSC];

    #pragma unroll
    for (int t = 0; t < NSC; ++t) {
        int row = __shfl_sync(0xffffffffu, idx, NCTX + t);
        const float4* r = reinterpret_cast<const float4*>(cen_w + (size_t)row * EMBED);
        float4 a0 = ldg_hint(r + lane,      pol_resident);
        float4 a1 = ldg_hint(r + lane + 32, pol_resident);
        float s = dot4(a0, cm0) + dot4(a1, cm1);
        if (tail) {
            float4 a2 = ldg_hint(r + lane + 64, pol_resident);
            s += dot4(a2, cm2);
        }
        #pragma unroll
        for (int off = 16; off > 0; off >>= 1)
            s += __shfl_xor_sync(0xffffffffu, s, off);
        if (lane == 0) sh_s[warp][t] = s;
    }
    __syncwarp();

    // ---- parallel log-sigmoids: one per lane ----
    float l = 0.0f;
    if (lane < NSC) {
        float s = sh_s[warp][lane];
        l = log_sigmoid(lane == 0 ? s : -s);
    }
    #pragma unroll
    for (int off = 16; off > 0; off >>= 1)
        l += __shfl_xor_sync(0xffffffffu, l, off);

    __shared__ float sdata[WARPS_PER_BLOCK];
    if (lane == 0) sdata[warp] = -l;
    __syncthreads();

    // ---- fused grid reduction: last block finalizes ----
    if (threadIdx.x == 0) {
        float tot = 0.f;
        #pragma unroll
        for (int i = 0; i < WARPS_PER_BLOCK; ++i) tot += sdata[i];

        atomicAdd(&g_sum, tot);
        __threadfence();
        unsigned prev = atomicAdd(&g_arrived, 1u);
        if (prev == GRID_BLOCKS - 1) {
            float total = g_sum;
            out[0] = total / (float)BATCH;
            g_sum = 0.0f;
            __threadfence();
            g_arrived = 0u;
        }
    }
}

extern "C" void kernel_launch(void* const* d_in, const int* in_sizes, int n_in,
                              void* d_out, int out_size)
{
    const int*   context   = (const int*)  d_in[0];
    const int*   center    = (const int*)  d_in[1];
    const int*   negatives = (const int*)  d_in[2];
    const float* ctx_w     = (const float*)d_in[3];
    const float* cen_w     = (const float*)d_in[4];
    float*       out       = (float*)d_out;

    cbow_fused_kernel<<<GRID_BLOCKS, BLOCK_THREADS>>>(
        context, center, negatives, ctx_w, cen_w, out);
}